// round 1
// baseline (speedup 1.0000x reference)
#include <cuda_runtime.h>
#include <math.h>
#include <stdint.h>

#define NMAX 100000
#define FEATD 64

// Scratch: per-node P (cols 0..63, includes b1) and Q (cols 64..127). 51.2 MB.
__device__ float g_PQ[(size_t)NMAX * 128];
__device__ int g_is64;

// ---------------------------------------------------------------------------
// Detect whether edge_index is int64 or int32 (jax x64-disabled emits int32).
// If int64 (values < 2^31), every odd int32 word of the first 8KB is zero.
// ---------------------------------------------------------------------------
__global__ void detect_kernel(const unsigned int* __restrict__ ei) {
    __shared__ int any;
    if (threadIdx.x == 0) any = 0;
    __syncthreads();
    int i = threadIdx.x;  // 1024 threads
    if (ei[2 * i + 1] != 0u) any = 1;  // benign race
    __syncthreads();
    if (threadIdx.x == 0) g_is64 = (any == 0) ? 1 : 0;
}

// ---------------------------------------------------------------------------
// Node kernel: PQ[n] = [ x@(W1a-W1b)+b1 | x@W1b ],  x = [feat(64) | xyz(3)]
// Block: 256 threads, 32 nodes x 128 cols, 4x4 register tile per thread.
// ---------------------------------------------------------------------------
__global__ __launch_bounds__(256) void node_pq_kernel(
    const float* __restrict__ xyz, const float* __restrict__ feat,
    const float* __restrict__ W1, const float* __restrict__ b1, int N) {
    __shared__ float ws[67][128];  // combined weights
    __shared__ float xs[32][68];   // padded rows

    int tid = threadIdx.x;
    for (int i = tid; i < 67 * 128; i += 256) {
        int k = i >> 7, c = i & 127;
        float w1b = W1[(k + 67) * 64 + (c & 63)];
        ws[k][c] = (c < 64) ? (W1[k * 64 + c] - w1b) : w1b;
    }
    int n0 = blockIdx.x * 32;
    for (int i = tid; i < 32 * 67; i += 256) {
        int n = i / 67, k = i - n * 67;
        int gn = n0 + n;
        float v = 0.f;
        if (gn < N) v = (k < 64) ? feat[(size_t)gn * 64 + k]
                                 : xyz[(size_t)gn * 3 + (k - 64)];
        xs[n][k] = v;
    }
    __syncthreads();

    int cg = tid & 31, ng = tid >> 5;
    int c0 = cg * 4, nr = ng * 4;
    float acc[4][4];
#pragma unroll
    for (int i = 0; i < 4; i++)
#pragma unroll
        for (int j = 0; j < 4; j++)
            acc[i][j] = (c0 < 64) ? b1[c0 + j] : 0.f;

#pragma unroll 67
    for (int k = 0; k < 67; k++) {
        float4 w = *(const float4*)&ws[k][c0];
#pragma unroll
        for (int i = 0; i < 4; i++) {
            float xv = xs[nr + i][k];
            acc[i][0] = fmaf(xv, w.x, acc[i][0]);
            acc[i][1] = fmaf(xv, w.y, acc[i][1]);
            acc[i][2] = fmaf(xv, w.z, acc[i][2]);
            acc[i][3] = fmaf(xv, w.w, acc[i][3]);
        }
    }
#pragma unroll
    for (int i = 0; i < 4; i++) {
        int gn = n0 + nr + i;
        if (gn < N) {
            float4 v = make_float4(acc[i][0], acc[i][1], acc[i][2], acc[i][3]);
            *(float4*)&g_PQ[(size_t)gn * 128 + c0] = v;
        }
    }
}

// ---------------------------------------------------------------------------
// Init output to -inf bit pattern
// ---------------------------------------------------------------------------
__global__ void init_kernel(unsigned int* __restrict__ out, int n) {
    int i = blockIdx.x * blockDim.x + threadIdx.x;
    if (i < n) out[i] = 0xff800000u;
}

// ---------------------------------------------------------------------------
// Float atomic max via int/uint ordering trick, with monotonic-safe pre-check.
// Values only grow -> a stale (older, smaller) read can never cause a wrong
// skip; it only avoids redundant atomics (~5x reduction for avg degree 16).
// ---------------------------------------------------------------------------
__device__ __forceinline__ void atomic_max_f(float* a, float v) {
    float cur = *a;
    if (v > cur) {
        if (v >= 0.f)
            atomicMax((int*)a, __float_as_int(v));
        else
            atomicMin((unsigned int*)a, __float_as_uint(v));
    }
}

// ---------------------------------------------------------------------------
// Edge kernel: one warp processes 2 edges per iteration.
//   z = relu(P[dst] + Q[src])   (z[k] in lane k regs, 2 regs/lane)
//   y = z @ W2 + b2             (W2 fully register-resident: 128 regs/lane,
//                                lane owns cols {lane, lane+32}; z via shfl)
//   scatter-max into out[dst]
// ---------------------------------------------------------------------------
__global__ __launch_bounds__(128, 3) void edge_kernel(
    const void* __restrict__ eidx, const float* __restrict__ W2,
    const float* __restrict__ b2, float* __restrict__ out, int E) {
    const int lane = threadIdx.x & 31;

    float wA[64], wB[64];
#pragma unroll
    for (int k = 0; k < 64; k++) {
        wA[k] = W2[k * 64 + lane];
        wB[k] = W2[k * 64 + 32 + lane];
    }
    const float bA = b2[lane], bB = b2[32 + lane];
    const bool is64 = (g_is64 != 0);
    const long long* e64 = (const long long*)eidx;
    const int* e32 = (const int*)eidx;

    int warpId = (blockIdx.x * blockDim.x + threadIdx.x) >> 5;
    int nwarp = (gridDim.x * blockDim.x) >> 5;
    int npair = (E + 1) >> 1;

    for (int p = warpId; p < npair; p += nwarp) {
        int ea = 2 * p;
        int eb = (ea + 1 < E) ? ea + 1 : ea;
        int sa, da, sb, db;
        if (is64) {
            sa = (int)e64[ea]; da = (int)e64[E + ea];
            sb = (int)e64[eb]; db = (int)e64[E + eb];
        } else {
            sa = e32[ea]; da = e32[E + ea];
            sb = e32[eb]; db = e32[E + eb];
        }
        const float* Pa = g_PQ + (size_t)da * 128;
        const float* Qa = g_PQ + (size_t)sa * 128 + 64;
        const float* Pb = g_PQ + (size_t)db * 128;
        const float* Qb = g_PQ + (size_t)sb * 128 + 64;

        float za0 = fmaxf(Pa[lane] + Qa[lane], 0.f);
        float za1 = fmaxf(Pa[lane + 32] + Qa[lane + 32], 0.f);
        float zb0 = fmaxf(Pb[lane] + Qb[lane], 0.f);
        float zb1 = fmaxf(Pb[lane + 32] + Qb[lane + 32], 0.f);

        float aa0 = bA, aa1 = bB, ab0 = bA, ab1 = bB;
#pragma unroll
        for (int k = 0; k < 32; k++) {
            float zka = __shfl_sync(0xffffffffu, za0, k);
            float zkb = __shfl_sync(0xffffffffu, zb0, k);
            aa0 = fmaf(zka, wA[k], aa0);
            aa1 = fmaf(zka, wB[k], aa1);
            ab0 = fmaf(zkb, wA[k], ab0);
            ab1 = fmaf(zkb, wB[k], ab1);
        }
#pragma unroll
        for (int k = 0; k < 32; k++) {
            float zka = __shfl_sync(0xffffffffu, za1, k);
            float zkb = __shfl_sync(0xffffffffu, zb1, k);
            aa0 = fmaf(zka, wA[32 + k], aa0);
            aa1 = fmaf(zka, wB[32 + k], aa1);
            ab0 = fmaf(zkb, wA[32 + k], ab0);
            ab1 = fmaf(zkb, wB[32 + k], ab1);
        }

        float* oa = out + (size_t)da * 64;
        atomic_max_f(oa + lane, aa0);
        atomic_max_f(oa + 32 + lane, aa1);
        if (eb != ea) {
            float* ob = out + (size_t)db * 64;
            atomic_max_f(ob + lane, ab0);
            atomic_max_f(ob + 32 + lane, ab1);
        }
    }
}

// ---------------------------------------------------------------------------
// Finalize: nodes with no incoming edges (still -inf) -> 0
// ---------------------------------------------------------------------------
__global__ void finalize_kernel(unsigned int* __restrict__ out, int n) {
    int i = blockIdx.x * blockDim.x + threadIdx.x;
    if (i < n && out[i] == 0xff800000u) out[i] = 0u;
}

// ---------------------------------------------------------------------------
// Inputs: [0]=xyz (N*3 f32), [1]=feat (N*64 f32), [2]=edge_index (2*E int),
//         [3]=W1 (134*64 f32), [4]=b1 (64), [5]=W2 (64*64), [6]=b2 (64)
// ---------------------------------------------------------------------------
extern "C" void kernel_launch(void* const* d_in, const int* in_sizes, int n_in,
                              void* d_out, int out_size) {
    const float* xyz  = (const float*)d_in[0];
    const float* feat = (const float*)d_in[1];
    const void*  eidx = d_in[2];
    const float* W1   = (const float*)d_in[3];
    const float* b1   = (const float*)d_in[4];
    const float* W2   = (const float*)d_in[5];
    const float* b2   = (const float*)d_in[6];
    float* out = (float*)d_out;

    int N = in_sizes[0] / 3;
    int E = in_sizes[2] / 2;
    int outn = N * 64;

    detect_kernel<<<1, 1024>>>((const unsigned int*)eidx);
    node_pq_kernel<<<(N + 31) / 32, 256>>>(xyz, feat, W1, b1, N);
    init_kernel<<<(outn + 255) / 256, 256>>>((unsigned int*)out, outn);
    edge_kernel<<<2048, 128>>>(eidx, W2, b2, out, E);
    finalize_kernel<<<(outn + 255) / 256, 256>>>((unsigned int*)out, outn);
}

// round 2
// speedup vs baseline: 1.2646x; 1.2646x over previous
#include <cuda_runtime.h>
#include <math.h>
#include <stdint.h>

#define NMAX 100000
#define EMAX 1700000
#define FEATD 64

// Scratch: per-node P (cols 0..63, includes b1) and Q (cols 64..127). 51.2 MB.
__device__ float g_PQ[(size_t)NMAX * 128];
__device__ int2 g_edges[EMAX];  // packed (src, dst) as int32
__device__ int g_is64;

// ---------------------------------------------------------------------------
// Detect whether edge_index is int64 or int32 (jax x64-disabled emits int32).
// If int64 (values < 2^31), every odd int32 word of the first 8KB is zero.
// ---------------------------------------------------------------------------
__global__ void detect_kernel(const unsigned int* __restrict__ ei) {
    __shared__ int any;
    if (threadIdx.x == 0) any = 0;
    __syncthreads();
    int i = threadIdx.x;  // 1024 threads
    if (ei[2 * i + 1] != 0u) any = 1;  // benign race
    __syncthreads();
    if (threadIdx.x == 0) g_is64 = (any == 0) ? 1 : 0;
}

// ---------------------------------------------------------------------------
// Convert edge_index (either width) into packed int2 (src, dst).
// ---------------------------------------------------------------------------
__global__ void conv_edges_kernel(const void* __restrict__ eidx, int E) {
    int i = blockIdx.x * blockDim.x + threadIdx.x;
    if (i >= E) return;
    int s, d;
    if (g_is64) {
        const long long* e64 = (const long long*)eidx;
        s = (int)e64[i];
        d = (int)e64[E + i];
    } else {
        const int* e32 = (const int*)eidx;
        s = e32[i];
        d = e32[E + i];
    }
    g_edges[i] = make_int2(s, d);
}

// ---------------------------------------------------------------------------
// Node kernel: PQ[n] = [ x@(W1a-W1b)+b1 | x@W1b ],  x = [feat(64) | xyz(3)]
// Block: 256 threads, 32 nodes x 128 cols, 4x4 register tile per thread.
// ---------------------------------------------------------------------------
__global__ __launch_bounds__(256) void node_pq_kernel(
    const float* __restrict__ xyz, const float* __restrict__ feat,
    const float* __restrict__ W1, const float* __restrict__ b1, int N) {
    __shared__ float ws[67][128];  // combined weights
    __shared__ float xs[32][68];   // padded rows

    int tid = threadIdx.x;
    for (int i = tid; i < 67 * 128; i += 256) {
        int k = i >> 7, c = i & 127;
        float w1b = W1[(k + 67) * 64 + (c & 63)];
        ws[k][c] = (c < 64) ? (W1[k * 64 + c] - w1b) : w1b;
    }
    int n0 = blockIdx.x * 32;
    for (int i = tid; i < 32 * 67; i += 256) {
        int n = i / 67, k = i - n * 67;
        int gn = n0 + n;
        float v = 0.f;
        if (gn < N) v = (k < 64) ? feat[(size_t)gn * 64 + k]
                                 : xyz[(size_t)gn * 3 + (k - 64)];
        xs[n][k] = v;
    }
    __syncthreads();

    int cg = tid & 31, ng = tid >> 5;
    int c0 = cg * 4, nr = ng * 4;
    float acc[4][4];
#pragma unroll
    for (int i = 0; i < 4; i++)
#pragma unroll
        for (int j = 0; j < 4; j++)
            acc[i][j] = (c0 < 64) ? b1[c0 + j] : 0.f;

#pragma unroll 67
    for (int k = 0; k < 67; k++) {
        float4 w = *(const float4*)&ws[k][c0];
#pragma unroll
        for (int i = 0; i < 4; i++) {
            float xv = xs[nr + i][k];
            acc[i][0] = fmaf(xv, w.x, acc[i][0]);
            acc[i][1] = fmaf(xv, w.y, acc[i][1]);
            acc[i][2] = fmaf(xv, w.z, acc[i][2]);
            acc[i][3] = fmaf(xv, w.w, acc[i][3]);
        }
    }
#pragma unroll
    for (int i = 0; i < 4; i++) {
        int gn = n0 + nr + i;
        if (gn < N) {
            float4 v = make_float4(acc[i][0], acc[i][1], acc[i][2], acc[i][3]);
            *(float4*)&g_PQ[(size_t)gn * 128 + c0] = v;
        }
    }
}

// ---------------------------------------------------------------------------
// Init output to -inf bit pattern
// ---------------------------------------------------------------------------
__global__ void init_kernel(unsigned int* __restrict__ out, int n) {
    int i = blockIdx.x * blockDim.x + threadIdx.x;
    if (i < n) out[i] = 0xff800000u;
}

// ---------------------------------------------------------------------------
// Float atomic max via int/uint ordering trick with pre-checked current value.
// Values only grow monotonically, so a STALE (older, smaller) pre-check value
// can only cause an extra (redundant) atomic, never a wrong skip.
// ---------------------------------------------------------------------------
__device__ __forceinline__ void atomic_max_f(float* a, float v, float cur) {
    if (v > cur) {
        if (v >= 0.f)
            atomicMax((int*)a, __float_as_int(v));
        else
            atomicMin((unsigned int*)a, __float_as_uint(v));
    }
}

// ---------------------------------------------------------------------------
// Edge kernel: one warp processes 2 edges per iteration, software-pipelined.
//   z = relu(P[dst] + Q[src])     -> staged in per-warp shared memory
//   y = z @ W2 + b2               -> W2 register-resident (128 regs/lane,
//                                    lane owns cols {lane, lane+32});
//                                    z read back as broadcast LDS.128
//   scatter-max into out[dst]     -> pre-check values prefetched one iter ahead
// Long-latency loads (edge pair, 8x P/Q rows, 4x out pre-check values) for
// iteration p+1 are issued before the 256-FMA loop of iteration p.
// ---------------------------------------------------------------------------
__global__ __launch_bounds__(128, 3) void edge_kernel(
    const float* __restrict__ W2, const float* __restrict__ b2,
    float* __restrict__ out, int E) {
    const int lane = threadIdx.x & 31;
    const int wInB = (threadIdx.x >> 5);

    __shared__ float zbuf[4][2][64];  // [warp][edge][dim]

    float wA[64], wB[64];
#pragma unroll
    for (int k = 0; k < 64; k++) {
        wA[k] = W2[k * 64 + lane];
        wB[k] = W2[k * 64 + 32 + lane];
    }
    const float bA = b2[lane], bB = b2[32 + lane];

    int warpId = (blockIdx.x * blockDim.x + threadIdx.x) >> 5;
    int nwarp = (gridDim.x * blockDim.x) >> 5;
    int npair = (E + 1) >> 1;

    float* zA = &zbuf[wInB][0][0];
    float* zB = &zbuf[wInB][1][0];

    if (warpId >= npair) return;

    // ---- prologue: load iteration-0 operands ----
    int p = warpId;
    int ea = 2 * p;
    int eb = (ea + 1 < E) ? ea + 1 : ea;
    int2 ia = g_edges[ea];
    int2 ib = g_edges[eb];
    const float* Pa = g_PQ + (size_t)ia.y * 128;
    const float* Qa = g_PQ + (size_t)ia.x * 128 + 64;
    const float* Pb = g_PQ + (size_t)ib.y * 128;
    const float* Qb = g_PQ + (size_t)ib.x * 128 + 64;
    float pa0 = Pa[lane], qa0 = Qa[lane];
    float pa1 = Pa[lane + 32], qa1 = Qa[lane + 32];
    float pb0 = Pb[lane], qb0 = Qb[lane];
    float pb1 = Pb[lane + 32], qb1 = Qb[lane + 32];
    float* oa = out + (size_t)ia.y * 64;
    float* ob = out + (size_t)ib.y * 64;
    float oc0 = oa[lane], oc1 = oa[lane + 32];
    float oc2 = ob[lane], oc3 = ob[lane + 32];

    while (true) {
        // ---- stage z in shared memory ----
        zA[lane]      = fmaxf(pa0 + qa0, 0.f);
        zA[lane + 32] = fmaxf(pa1 + qa1, 0.f);
        zB[lane]      = fmaxf(pb0 + qb0, 0.f);
        zB[lane + 32] = fmaxf(pb1 + qb1, 0.f);
        __syncwarp();

        // ---- prefetch next iteration's operands ----
        int pn = p + nwarp;
        bool more = (pn < npair);
        int2 na = ia, nb = ib;  // keep dst for this iteration's atomics
        float npa0 = 0, nqa0 = 0, npa1 = 0, nqa1 = 0;
        float npb0 = 0, nqb0 = 0, npb1 = 0, nqb1 = 0;
        float noc0 = 0, noc1 = 0, noc2 = 0, noc3 = 0;
        float *noa = oa, *nob = ob;
        if (more) {
            int nea = 2 * pn;
            int neb = (nea + 1 < E) ? nea + 1 : nea;
            int2 ja = g_edges[nea];
            int2 jb = g_edges[neb];
            na = ja; nb = jb;
            const float* nPa = g_PQ + (size_t)ja.y * 128;
            const float* nQa = g_PQ + (size_t)ja.x * 128 + 64;
            const float* nPb = g_PQ + (size_t)jb.y * 128;
            const float* nQb = g_PQ + (size_t)jb.x * 128 + 64;
            npa0 = nPa[lane]; nqa0 = nQa[lane];
            npa1 = nPa[lane + 32]; nqa1 = nQa[lane + 32];
            npb0 = nPb[lane]; nqb0 = nQb[lane];
            npb1 = nPb[lane + 32]; nqb1 = nQb[lane + 32];
            noa = out + (size_t)ja.y * 64;
            nob = out + (size_t)jb.y * 64;
            noc0 = noa[lane]; noc1 = noa[lane + 32];
            noc2 = nob[lane]; noc3 = nob[lane + 32];
        }

        // ---- 256-FMA GEMV: y = z @ W2 + b2 (z via broadcast LDS.128) ----
        float aa0 = bA, aa1 = bB, ab0 = bA, ab1 = bB;
#pragma unroll
        for (int k4 = 0; k4 < 16; k4++) {
            float4 za = *(const float4*)&zA[4 * k4];
            float4 zb = *(const float4*)&zB[4 * k4];
#pragma unroll
            for (int j = 0; j < 4; j++) {
                float zaj = (&za.x)[j];
                float zbj = (&zb.x)[j];
                aa0 = fmaf(zaj, wA[4 * k4 + j], aa0);
                aa1 = fmaf(zaj, wB[4 * k4 + j], aa1);
                ab0 = fmaf(zbj, wA[4 * k4 + j], ab0);
                ab1 = fmaf(zbj, wB[4 * k4 + j], ab1);
            }
        }
        __syncwarp();  // zbuf reads done before next iteration's STS

        // ---- scatter-max (pre-check values were prefetched) ----
        float* coa = out + (size_t)ia.y * 64;
        atomic_max_f(coa + lane, aa0, oc0);
        atomic_max_f(coa + 32 + lane, aa1, oc1);
        if (2 * p + 1 < E) {
            float* cob = out + (size_t)ib.y * 64;
            atomic_max_f(cob + lane, ab0, oc2);
            atomic_max_f(cob + 32 + lane, ab1, oc3);
        }

        if (!more) break;
        // ---- rotate pipeline registers ----
        p = pn;
        ia = na; ib = nb;
        pa0 = npa0; qa0 = nqa0; pa1 = npa1; qa1 = nqa1;
        pb0 = npb0; qb0 = nqb0; pb1 = npb1; qb1 = nqb1;
        oc0 = noc0; oc1 = noc1; oc2 = noc2; oc3 = noc3;
        oa = noa; ob = nob;
    }
}

// ---------------------------------------------------------------------------
// Finalize: nodes with no incoming edges (still -inf) -> 0
// ---------------------------------------------------------------------------
__global__ void finalize_kernel(unsigned int* __restrict__ out, int n) {
    int i = blockIdx.x * blockDim.x + threadIdx.x;
    if (i < n && out[i] == 0xff800000u) out[i] = 0u;
}

// ---------------------------------------------------------------------------
// Inputs: [0]=xyz (N*3 f32), [1]=feat (N*64 f32), [2]=edge_index (2*E int),
//         [3]=W1 (134*64 f32), [4]=b1 (64), [5]=W2 (64*64), [6]=b2 (64)
// ---------------------------------------------------------------------------
extern "C" void kernel_launch(void* const* d_in, const int* in_sizes, int n_in,
                              void* d_out, int out_size) {
    const float* xyz  = (const float*)d_in[0];
    const float* feat = (const float*)d_in[1];
    const void*  eidx = d_in[2];
    const float* W1   = (const float*)d_in[3];
    const float* b1   = (const float*)d_in[4];
    const float* W2   = (const float*)d_in[5];
    const float* b2   = (const float*)d_in[6];
    float* out = (float*)d_out;

    int N = in_sizes[0] / 3;
    int E = in_sizes[2] / 2;
    int outn = N * 64;

    detect_kernel<<<1, 1024>>>((const unsigned int*)eidx);
    conv_edges_kernel<<<(E + 255) / 256, 256>>>(eidx, E);
    node_pq_kernel<<<(N + 31) / 32, 256>>>(xyz, feat, W1, b1, N);
    init_kernel<<<(outn + 255) / 256, 256>>>((unsigned int*)out, outn);
    edge_kernel<<<2048, 128>>>(W2, b2, out, E);
    finalize_kernel<<<(outn + 255) / 256, 256>>>((unsigned int*)out, outn);
}